// round 6
// baseline (speedup 1.0000x reference)
#include <cuda_runtime.h>
#include <cstdint>

// ---------------------------------------------------------------------------
// QuanvolutionClassifier, phase form:
//   logits[b,c] = bias[c] + sum_px (w[c,px]*R_w) * cos(x[b,px] - phi_w)
// Round 6: SPLIT=4 (196 px/CTA), 4 CTAs/SM (regs<=64, smem 35.5KB),
// monolithic cp.async x stage, fused counter-based finalize.
// ---------------------------------------------------------------------------

#define THREADS 256
#define WARPS 8
#define SPLIT 4
#define PX_CTA 196
#define NF4 49                        // float4 quads per CTA slice
#define XP4 51                        // x pitch in float4 (conflict-free)
#define MAXB 8192
#define NGRP (MAXB / 32)

#define SW_FLOATS (PX_CTA * 12)       // 2352 floats = 9408 B
#define SX_BYTES (32 * XP4 * 16)      // 26112 B
#define SMEM_BYTES (SW_FLOATS * 4 + SX_BYTES)   // 35520

__device__ float g_part[SPLIT][MAXB][10];
__device__ unsigned int g_flag[NGRP];

typedef unsigned long long u64;

__device__ __forceinline__ u64 pack2(float x, float y) {
    u64 r; asm("mov.b64 %0, {%1, %2};" : "=l"(r) : "f"(x), "f"(y)); return r;
}
__device__ __forceinline__ u64 fma2(u64 a, u64 b, u64 c) {
    u64 d; asm("fma.rn.f32x2 %0, %1, %2, %3;" : "=l"(d) : "l"(a), "l"(b), "l"(c)); return d;
}
__device__ __forceinline__ float2 unpack2(u64 v) {
    float2 f; asm("mov.b64 {%0, %1}, %2;" : "=f"(f.x), "=f"(f.y) : "l"(v)); return f;
}
__device__ __forceinline__ void cp_async16(uint32_t saddr, const void* gaddr) {
    asm volatile("cp.async.cg.shared.global [%0], [%1], 16;" :: "r"(saddr), "l"(gaddr));
}

struct c2f { float x, y; };
__device__ __forceinline__ c2f cmulf(c2f a, c2f b) {
    return { a.x * b.x - a.y * b.y, a.x * b.y + a.y * b.x };
}

// ---------------------------------------------------------------------------
__global__ void __launch_bounds__(THREADS, 4)
quanv_kernel(const float* __restrict__ x,
             const float* __restrict__ params,
             const float* __restrict__ wmat,
             const float* __restrict__ bias,
             float* __restrict__ out,
             int B, int depth) {
    extern __shared__ float smem[];
    float* sW  = smem;                                 // PX_CTA*12
    float* sXf = smem + SW_FLOATS;                     // 32 rows x XP4 float4
    float* sP  = smem + SW_FLOATS;                     // partials overlay
    __shared__ float sRP[8];
    __shared__ float sParams[64];
    __shared__ unsigned int sArriv;

    int tid = threadIdx.x;
    int warp = tid >> 5, lane = tid & 31;
    int part = blockIdx.x & (SPLIT - 1);
    int grp  = blockIdx.x >> 2;
    int b0 = grp * 32;
    int pxBase = part * PX_CTA;

    // ---- 1. stage all x via cp.async: 1568 float4, 7 per thread ----
    {
        uint32_t sbase = (uint32_t)__cvta_generic_to_shared(sXf);
#pragma unroll
        for (int k = 0; k < 7; ++k) {
            int i = tid + k * THREADS;
            if (i < 32 * NF4) {
                int s = i / NF4, j = i - s * NF4;
                int b = b0 + s; if (b >= B) b = B - 1;
                const float* g = x + (size_t)b * 784 + pxBase + j * 4;
                cp_async16(sbase + (uint32_t)(s * XP4 + j) * 16u, g);
            }
        }
        asm volatile("cp.async.commit_group;");
    }

    // ---- 2. wmat gather -> smem raw (no live regs held) ----
#pragma unroll
    for (int j = 0; j < 8; ++j) {
        int i = tid + j * THREADS;
        if (i < PX_CTA * 10) {
            int px = i / 10, c = i - px * 10;
            int gpx = pxBase + px;
            int r = gpx / 28, cc = gpx - r * 28;
            int wi = (r & 1) * 2 + (cc & 1);
            int k = ((r >> 1) * 14 + (cc >> 1)) * 4 + wi;
            sW[px * 12 + c] = __ldg(&wmat[c * 784 + k]);
        }
    }

    // ---- 3. params -> smem ----
    int np = 12 * depth;
    if (tid < np && tid < 64) sParams[tid] = params[tid];
    __syncthreads();

    // ---- 4. wires 0..3: SU(2) composition -> (R, phi) ----
    if (tid < 4) {
        int wire = tid;
        c2f a0{1.f, 0.f}, b0c{0.f, 0.f};
        c2f a1{0.f, 0.f}, b1{1.f, 0.f};
        for (int d = 0; d < depth; ++d) {
            float rz1 = sParams[(d * 4 + wire) * 3 + 0];
            float ry  = sParams[(d * 4 + wire) * 3 + 1];
            float rz2 = sParams[(d * 4 + wire) * 3 + 2];
            float c1v, s1v; __sincosf(0.5f * rz1, &s1v, &c1v);
            c2f p1{c1v, -s1v}, p1c{c1v, s1v};
            a0 = cmulf(a0, p1);  a1 = cmulf(a1, p1);
            b0c = cmulf(b0c, p1c); b1 = cmulf(b1, p1c);
            float cy, sy; __sincosf(0.5f * ry, &sy, &cy);
            c2f na0{cy * a0.x - sy * b0c.x, cy * a0.y - sy * b0c.y};
            c2f nb0{sy * a0.x + cy * b0c.x, sy * a0.y + cy * b0c.y};
            c2f na1{cy * a1.x - sy * b1.x, cy * a1.y - sy * b1.y};
            c2f nb1{sy * a1.x + cy * b1.x, sy * a1.y + cy * b1.y};
            a0 = na0; b0c = nb0; a1 = na1; b1 = nb1;
            float cz, sz; __sincosf(0.5f * rz2, &sz, &cz);
            c2f p2{cz, -sz}, p2c{cz, sz};
            a0 = cmulf(a0, p2);  a1 = cmulf(a1, p2);
            b0c = cmulf(b0c, p2c); b1 = cmulf(b1, p2c);
        }
        float al = 2.f * (a0.x * a0.x + a0.y * a0.y) - 1.f;
        float be = 2.f * (a0.x * a1.x + a0.y * a1.y);
        sRP[wire]     = sqrtf(al * al + be * be);
        sRP[4 + wire] = atan2f(be, al);
    }
    __syncthreads();

    // ---- 5. fold in place: w *= R ; store phi ----
#pragma unroll
    for (int j = 0; j < 8; ++j) {
        int i = tid + j * THREADS;
        if (i < PX_CTA * 10) {
            int px = i / 10;
            int gpx = pxBase + px;
            int r = gpx / 28, cc = gpx - r * 28;
            int wi = (r & 1) * 2 + (cc & 1);
            sW[i + px * 2] *= sRP[wi];   // i + px*2 == px*12 + c
        }
    }
    if (tid < PX_CTA) {
        int gpx = pxBase + tid;
        int r = gpx / 28, cc = gpx - r * 28;
        int wi = (r & 1) * 2 + (cc & 1);
        sW[tid * 12 + 10] = sRP[4 + wi];
        sW[tid * 12 + 11] = 0.f;
    }
    asm volatile("cp.async.wait_group 0;");
    __syncthreads();

    // ---- 6. compute: warp w owns quads j = w, w+8, ... (<49) ----
    u64 acc[5] = {0ull, 0ull, 0ull, 0ull, 0ull};
    const float4* xrow = reinterpret_cast<const float4*>(sXf) + lane * XP4;

#define PROC_PX(pval, pxi)                                                   \
    {                                                                        \
        const ulonglong2* wp =                                               \
            reinterpret_cast<const ulonglong2*>(sW + (pxi) * 12);            \
        ulonglong2 q0 = wp[0], q1 = wp[1], q2 = wp[2];                       \
        float2 ph = unpack2(q2.y);                                           \
        float z = __cosf((pval) - ph.x);                                     \
        u64 zz = pack2(z, z);                                                \
        acc[0] = fma2(q0.x, zz, acc[0]);                                     \
        acc[1] = fma2(q0.y, zz, acc[1]);                                     \
        acc[2] = fma2(q1.x, zz, acc[2]);                                     \
        acc[3] = fma2(q1.y, zz, acc[3]);                                     \
        acc[4] = fma2(q2.x, zz, acc[4]);                                     \
    }

#pragma unroll
    for (int t = 0; t < 7; ++t) {
        int j = warp + t * 8;
        if (j < NF4) {
            float4 xv = xrow[j];
            int pxl = j * 4;
            PROC_PX(xv.x, pxl + 0);
            PROC_PX(xv.y, pxl + 1);
            PROC_PX(xv.z, pxl + 2);
            PROC_PX(xv.w, pxl + 3);
        }
    }
#undef PROC_PX

    // ---- 7. per-warp partials -> smem (overlay, protected by sync) ----
    __syncthreads();
    {
        float2* pp = reinterpret_cast<float2*>(sP + (warp * 32 + lane) * 10);
#pragma unroll
        for (int j = 0; j < 5; ++j) pp[j] = unpack2(acc[j]);
    }
    __syncthreads();

    // ---- 8. reduce 8 warps -> global partial scratch ----
    for (int idx = tid; idx < 320; idx += THREADS) {
        int s = idx / 10, c = idx - s * 10;
        float v = 0.f;
#pragma unroll
        for (int w = 0; w < WARPS; ++w) v += sP[(w * 32 + s) * 10 + c];
        int b = b0 + s;
        if (b < B && b < MAXB) g_part[part][b][c] = v;
    }

    // ---- 9. completion counter: last CTA of group finalizes ----
    __threadfence();
    __syncthreads();
    if (tid == 0) sArriv = atomicAdd(&g_flag[grp], 1u);
    __syncthreads();
    if (sArriv == SPLIT - 1) {
        if (tid < 32) {
            int b = b0 + tid;
            if (b < B) {
                float L[10];
#pragma unroll
                for (int c = 0; c < 10; ++c) {
                    float v = __ldg(&bias[c]);
#pragma unroll
                    for (int p = 0; p < SPLIT; ++p) v += __ldcg(&g_part[p][b][c]);
                    L[c] = v;
                }
                float m = L[0];
#pragma unroll
                for (int c = 1; c < 10; ++c) m = fmaxf(m, L[c]);
                float sum = 0.f;
#pragma unroll
                for (int c = 0; c < 10; ++c) sum += __expf(L[c] - m);
                float lse = m + __logf(sum);
#pragma unroll
                for (int c = 0; c < 10; ++c) out[(size_t)b * 10 + c] = L[c] - lse;
            }
        }
        if (tid == 0) g_flag[grp] = 0u;
    }
}

extern "C" void kernel_launch(void* const* d_in, const int* in_sizes, int n_in,
                              void* d_out, int out_size) {
    const float* x      = (const float*)d_in[0];
    const float* params = (const float*)d_in[1];
    const float* wmat   = (const float*)d_in[2];
    const float* bias   = (const float*)d_in[3];
    float* out = (float*)d_out;

    int B = in_sizes[0] / 784;
    int depth = in_sizes[1] / 12;

    cudaFuncSetAttribute(quanv_kernel,
                         cudaFuncAttributeMaxDynamicSharedMemorySize, SMEM_BYTES);

    int ngroups = (B + 31) / 32;
    quanv_kernel<<<ngroups * SPLIT, THREADS, SMEM_BYTES>>>(
        x, params, wmat, bias, out, B, depth);
}

// round 7
// speedup vs baseline: 1.0363x; 1.0363x over previous
#include <cuda_runtime.h>
#include <cstdint>

// ---------------------------------------------------------------------------
// QuanvolutionClassifier, phase form:
//   logits[b,c] = bias[c] + sum_px (w[c,px]*R_w) * cos(x[b,px] - phi_w)
// Round 7: 2-sample blocking (64 samples/CTA, lane handles s and s+32) to
// amortize broadcast weight LDS over 2 samples. SPLIT=4 px (196/CTA),
// grid=512, 3 CTAs/SM, cp.async monolithic x stage, fused finalize.
// ---------------------------------------------------------------------------

#define THREADS 256
#define WARPS 8
#define SPLIT 4
#define PX_CTA 196
#define NF4 49                        // float4 quads per CTA slice
#define XP4 51                        // x pitch in float4 (conflict-free)
#define SAMP 64                       // samples per CTA
#define MAXB 8192
#define NGRP (MAXB / SAMP)

#define SW_FLOATS (PX_CTA * 12)       // 2352 floats = 9408 B
#define SX_BYTES (SAMP * XP4 * 16)    // 52224 B
#define SMEM_BYTES (SW_FLOATS * 4 + SX_BYTES)   // 61632

__device__ float g_part[SPLIT][MAXB][10];
__device__ unsigned int g_flag[NGRP];

typedef unsigned long long u64;

__device__ __forceinline__ u64 pack2(float x, float y) {
    u64 r; asm("mov.b64 %0, {%1, %2};" : "=l"(r) : "f"(x), "f"(y)); return r;
}
__device__ __forceinline__ u64 fma2(u64 a, u64 b, u64 c) {
    u64 d; asm("fma.rn.f32x2 %0, %1, %2, %3;" : "=l"(d) : "l"(a), "l"(b), "l"(c)); return d;
}
__device__ __forceinline__ float2 unpack2(u64 v) {
    float2 f; asm("mov.b64 {%0, %1}, %2;" : "=f"(f.x), "=f"(f.y) : "l"(v)); return f;
}
__device__ __forceinline__ void cp_async16(uint32_t saddr, const void* gaddr) {
    asm volatile("cp.async.cg.shared.global [%0], [%1], 16;" :: "r"(saddr), "l"(gaddr));
}

struct c2f { float x, y; };
__device__ __forceinline__ c2f cmulf(c2f a, c2f b) {
    return { a.x * b.x - a.y * b.y, a.x * b.y + a.y * b.x };
}

// ---------------------------------------------------------------------------
__global__ void __launch_bounds__(THREADS, 3)
quanv_kernel(const float* __restrict__ x,
             const float* __restrict__ params,
             const float* __restrict__ wmat,
             const float* __restrict__ bias,
             float* __restrict__ out,
             int B, int depth) {
    extern __shared__ float smem[];
    float* sW  = smem;                                 // PX_CTA*12
    float* sXf = smem + SW_FLOATS;                     // SAMP rows x XP4 float4
    float* sP  = smem + SW_FLOATS;                     // partials overlay
    __shared__ float sRP[8];
    __shared__ float sParams[64];
    __shared__ unsigned int sArriv;

    int tid = threadIdx.x;
    int warp = tid >> 5, lane = tid & 31;
    int part = blockIdx.x & (SPLIT - 1);
    int grp  = blockIdx.x >> 2;
    int b0 = grp * SAMP;
    int pxBase = part * PX_CTA;

    // ---- 1. stage all x via cp.async: 64 rows x 49 f4 = 3136, 13/thread ----
    {
        uint32_t sbase = (uint32_t)__cvta_generic_to_shared(sXf);
#pragma unroll
        for (int k = 0; k < 13; ++k) {
            int i = tid + k * THREADS;
            if (i < SAMP * NF4) {
                int s = i / NF4, j = i - s * NF4;
                int b = b0 + s; if (b >= B) b = B - 1;
                const float* g = x + (size_t)b * 784 + pxBase + j * 4;
                cp_async16(sbase + (uint32_t)(s * XP4 + j) * 16u, g);
            }
        }
        asm volatile("cp.async.commit_group;");
    }

    // ---- 2. wmat gather -> smem raw ----
#pragma unroll
    for (int j = 0; j < 8; ++j) {
        int i = tid + j * THREADS;
        if (i < PX_CTA * 10) {
            int px = i / 10, c = i - px * 10;
            int gpx = pxBase + px;
            int r = gpx / 28, cc = gpx - r * 28;
            int wi = (r & 1) * 2 + (cc & 1);
            int k = ((r >> 1) * 14 + (cc >> 1)) * 4 + wi;
            sW[px * 12 + c] = __ldg(&wmat[c * 784 + k]);
        }
    }

    // ---- 3. params -> smem ----
    int np = 12 * depth;
    if (tid < np && tid < 64) sParams[tid] = params[tid];
    __syncthreads();

    // ---- 4. wires 0..3: SU(2) composition -> (R, phi) ----
    if (tid < 4) {
        int wire = tid;
        c2f a0{1.f, 0.f}, b0c{0.f, 0.f};
        c2f a1{0.f, 0.f}, b1{1.f, 0.f};
        for (int d = 0; d < depth; ++d) {
            float rz1 = sParams[(d * 4 + wire) * 3 + 0];
            float ry  = sParams[(d * 4 + wire) * 3 + 1];
            float rz2 = sParams[(d * 4 + wire) * 3 + 2];
            float c1v, s1v; __sincosf(0.5f * rz1, &s1v, &c1v);
            c2f p1{c1v, -s1v}, p1c{c1v, s1v};
            a0 = cmulf(a0, p1);  a1 = cmulf(a1, p1);
            b0c = cmulf(b0c, p1c); b1 = cmulf(b1, p1c);
            float cy, sy; __sincosf(0.5f * ry, &sy, &cy);
            c2f na0{cy * a0.x - sy * b0c.x, cy * a0.y - sy * b0c.y};
            c2f nb0{sy * a0.x + cy * b0c.x, sy * a0.y + cy * b0c.y};
            c2f na1{cy * a1.x - sy * b1.x, cy * a1.y - sy * b1.y};
            c2f nb1{sy * a1.x + cy * b1.x, sy * a1.y + cy * b1.y};
            a0 = na0; b0c = nb0; a1 = na1; b1 = nb1;
            float cz, sz; __sincosf(0.5f * rz2, &sz, &cz);
            c2f p2{cz, -sz}, p2c{cz, sz};
            a0 = cmulf(a0, p2);  a1 = cmulf(a1, p2);
            b0c = cmulf(b0c, p2c); b1 = cmulf(b1, p2c);
        }
        float al = 2.f * (a0.x * a0.x + a0.y * a0.y) - 1.f;
        float be = 2.f * (a0.x * a1.x + a0.y * a1.y);
        sRP[wire]     = sqrtf(al * al + be * be);
        sRP[4 + wire] = atan2f(be, al);
    }
    __syncthreads();

    // ---- 5. fold in place: w *= R ; store phi ----
#pragma unroll
    for (int j = 0; j < 8; ++j) {
        int i = tid + j * THREADS;
        if (i < PX_CTA * 10) {
            int px = i / 10;
            int gpx = pxBase + px;
            int r = gpx / 28, cc = gpx - r * 28;
            int wi = (r & 1) * 2 + (cc & 1);
            sW[i + px * 2] *= sRP[wi];   // i + px*2 == px*12 + c
        }
    }
    if (tid < PX_CTA) {
        int gpx = pxBase + tid;
        int r = gpx / 28, cc = gpx - r * 28;
        int wi = (r & 1) * 2 + (cc & 1);
        sW[tid * 12 + 10] = sRP[4 + wi];
        sW[tid * 12 + 11] = 0.f;
    }
    asm volatile("cp.async.wait_group 0;");
    __syncthreads();

    // ---- 6. compute: lane = samples (lane, lane+32); warp w: quads w,w+8,.. ----
    u64 accA[5] = {0ull, 0ull, 0ull, 0ull, 0ull};
    u64 accB[5] = {0ull, 0ull, 0ull, 0ull, 0ull};
    const float4* xrowA = reinterpret_cast<const float4*>(sXf) + lane * XP4;
    const float4* xrowB = reinterpret_cast<const float4*>(sXf) + (lane + 32) * XP4;

#define PROC_PX(pa, pb, pxi)                                                 \
    {                                                                        \
        const ulonglong2* wp =                                               \
            reinterpret_cast<const ulonglong2*>(sW + (pxi) * 12);            \
        ulonglong2 q0 = wp[0], q1 = wp[1], q2 = wp[2];                       \
        float2 ph = unpack2(q2.y);                                           \
        float za = __cosf((pa) - ph.x);                                      \
        float zb = __cosf((pb) - ph.x);                                      \
        u64 zza = pack2(za, za);                                             \
        u64 zzb = pack2(zb, zb);                                             \
        accA[0] = fma2(q0.x, zza, accA[0]);                                  \
        accB[0] = fma2(q0.x, zzb, accB[0]);                                  \
        accA[1] = fma2(q0.y, zza, accA[1]);                                  \
        accB[1] = fma2(q0.y, zzb, accB[1]);                                  \
        accA[2] = fma2(q1.x, zza, accA[2]);                                  \
        accB[2] = fma2(q1.x, zzb, accB[2]);                                  \
        accA[3] = fma2(q1.y, zza, accA[3]);                                  \
        accB[3] = fma2(q1.y, zzb, accB[3]);                                  \
        accA[4] = fma2(q2.x, zza, accA[4]);                                  \
        accB[4] = fma2(q2.x, zzb, accB[4]);                                  \
    }

#pragma unroll
    for (int t = 0; t < 7; ++t) {
        int j = warp + t * 8;
        if (j < NF4) {
            float4 xa = xrowA[j];
            float4 xb = xrowB[j];
            int pxl = j * 4;
            PROC_PX(xa.x, xb.x, pxl + 0);
            PROC_PX(xa.y, xb.y, pxl + 1);
            PROC_PX(xa.z, xb.z, pxl + 2);
            PROC_PX(xa.w, xb.w, pxl + 3);
        }
    }
#undef PROC_PX

    // ---- 7. per-warp partials -> smem (overlay on x, protected by sync) ----
    __syncthreads();
    {
        float2* ppA = reinterpret_cast<float2*>(sP + (warp * SAMP + lane) * 10);
        float2* ppB = reinterpret_cast<float2*>(sP + (warp * SAMP + lane + 32) * 10);
#pragma unroll
        for (int j = 0; j < 5; ++j) { ppA[j] = unpack2(accA[j]); ppB[j] = unpack2(accB[j]); }
    }
    __syncthreads();

    // ---- 8. reduce 8 warps -> global partial scratch ----
    for (int idx = tid; idx < SAMP * 10; idx += THREADS) {
        int s = idx / 10, c = idx - s * 10;
        float v = 0.f;
#pragma unroll
        for (int w = 0; w < WARPS; ++w) v += sP[(w * SAMP + s) * 10 + c];
        int b = b0 + s;
        if (b < B && b < MAXB) g_part[part][b][c] = v;
    }

    // ---- 9. completion counter: last CTA of group finalizes ----
    __threadfence();
    __syncthreads();
    if (tid == 0) sArriv = atomicAdd(&g_flag[grp], 1u);
    __syncthreads();
    if (sArriv == SPLIT - 1) {
        if (tid < SAMP) {
            int b = b0 + tid;
            if (b < B) {
                float L[10];
#pragma unroll
                for (int c = 0; c < 10; ++c) {
                    float v = __ldg(&bias[c]);
#pragma unroll
                    for (int p = 0; p < SPLIT; ++p) v += __ldcg(&g_part[p][b][c]);
                    L[c] = v;
                }
                float m = L[0];
#pragma unroll
                for (int c = 1; c < 10; ++c) m = fmaxf(m, L[c]);
                float sum = 0.f;
#pragma unroll
                for (int c = 0; c < 10; ++c) sum += __expf(L[c] - m);
                float lse = m + __logf(sum);
#pragma unroll
                for (int c = 0; c < 10; ++c) out[(size_t)b * 10 + c] = L[c] - lse;
            }
        }
        if (tid == 0) g_flag[grp] = 0u;
    }
}

extern "C" void kernel_launch(void* const* d_in, const int* in_sizes, int n_in,
                              void* d_out, int out_size) {
    const float* x      = (const float*)d_in[0];
    const float* params = (const float*)d_in[1];
    const float* wmat   = (const float*)d_in[2];
    const float* bias   = (const float*)d_in[3];
    float* out = (float*)d_out;

    int B = in_sizes[0] / 784;
    int depth = in_sizes[1] / 12;

    cudaFuncSetAttribute(quanv_kernel,
                         cudaFuncAttributeMaxDynamicSharedMemorySize, SMEM_BYTES);

    int ngroups = (B + SAMP - 1) / SAMP;
    quanv_kernel<<<ngroups * SPLIT, THREADS, SMEM_BYTES>>>(
        x, params, wmat, bias, out, B, depth);
}